// round 4
// baseline (speedup 1.0000x reference)
#include <cuda_runtime.h>

#define N      512
#define D      2048
#define LDIM   128
#define PARTS  8
#define SPLITS 4
#define KZ     (D / SPLITS)   // 512
#define BM     128
#define BN     64
#define BK     16
#define MARGIN 0.3f

// ---------------- device scratch (static allocation only) ----------------
__device__ float g_sq[N];
__device__ float g_gram[SPLITS][N * N];   // 4 MB: split-K partial Gram matrices
__device__ int   g_pi[N];
__device__ int   g_ni[N];

// packed f32x2 FMA: d.lo += a.lo*b.lo ; d.hi += a.hi*b.hi
__device__ __forceinline__ void fma2(unsigned long long& d,
                                     unsigned long long a,
                                     unsigned long long b) {
    asm("fma.rn.f32x2 %0, %1, %2, %0;" : "+l"(d) : "l"(a), "l"(b));
}
__device__ __forceinline__ unsigned long long pack2(float x, float y) {
    unsigned long long u;
    asm("mov.b64 %0, {%1,%2};" : "=l"(u) : "f"(x), "f"(y));
    return u;
}

// ---------------- kernel 0: zero the output accumulators ----------------
__global__ void init_out_kernel(float* out, int n) {
    int t = threadIdx.x;
    if (t < n) out[t] = 0.0f;
}

// ---------------- kernel 1: row squared norms ----------------
__global__ void norms_kernel(const float* __restrict__ X) {
    int i = blockIdx.x;
    int t = threadIdx.x;
    const float4* x4 = reinterpret_cast<const float4*>(X + (size_t)i * D);
    float4 a = x4[t];
    float4 b = x4[t + 256];
    float s = a.x * a.x + a.y * a.y + a.z * a.z + a.w * a.w
            + b.x * b.x + b.y * b.y + b.z * b.z + b.w * b.w;
#pragma unroll
    for (int o = 16; o > 0; o >>= 1) s += __shfl_down_sync(0xffffffffu, s, o);
    __shared__ float ws[8];
    if ((t & 31) == 0) ws[t >> 5] = s;
    __syncthreads();
    if (t < 8) {
        s = ws[t];
#pragma unroll
        for (int o = 4; o > 0; o >>= 1) s += __shfl_down_sync(0xffu, s, o);
        if (t == 0) g_sq[i] = s;
    }
}

// ---------------- kernel 2: split-K Gram (X @ X^T), FFMA2 packed ----------------
// 128 threads, tile BM=128 x BN=64, micro 8x8 per thread, k packed as float2.
__global__ void __launch_bounds__(128, 1)
gram_kernel(const float* __restrict__ X) {
    __shared__ unsigned long long As[BK / 2][BM + 1];  // [8][129] (k even/odd packed)
    __shared__ unsigned long long Bs[BK / 2][BN + 1];

    const int tid = threadIdx.x;
    const int tx  = tid & 7;    // 0..7  (col group)
    const int ty  = tid >> 3;   // 0..15 (row group)
    const int m0  = blockIdx.y * BM;
    const int n0  = blockIdx.x * BN;
    const int kz  = blockIdx.z * KZ;

    unsigned long long acc[8][8];
#pragma unroll
    for (int r = 0; r < 8; r++)
#pragma unroll
        for (int c = 0; c < 8; c++) acc[r][c] = 0ull;

    for (int kc = 0; kc < KZ / BK; kc++) {
        const int kb = kz + kc * BK;
        // load A tile: 128 rows x 16 k  (512 float4, 4 per thread)
#pragma unroll
        for (int l = 0; l < 4; l++) {
            int idx = tid + 128 * l;
            int row = idx >> 2;
            int c4  = idx & 3;
            float4 v = *reinterpret_cast<const float4*>(
                X + (size_t)(m0 + row) * D + kb + c4 * 4);
            As[c4 * 2][row]     = pack2(v.x, v.y);
            As[c4 * 2 + 1][row] = pack2(v.z, v.w);
        }
        // load B tile: 64 rows x 16 k (256 float4, 2 per thread)
#pragma unroll
        for (int l = 0; l < 2; l++) {
            int idx = tid + 128 * l;
            int row = idx >> 2;
            int c4  = idx & 3;
            float4 v = *reinterpret_cast<const float4*>(
                X + (size_t)(n0 + row) * D + kb + c4 * 4);
            Bs[c4 * 2][row]     = pack2(v.x, v.y);
            Bs[c4 * 2 + 1][row] = pack2(v.z, v.w);
        }
        __syncthreads();
#pragma unroll
        for (int k2 = 0; k2 < BK / 2; k2++) {
            unsigned long long a[8], b[8];
#pragma unroll
            for (int r = 0; r < 8; r++) a[r] = As[k2][ty + 16 * r];
#pragma unroll
            for (int c = 0; c < 8; c++) b[c] = Bs[k2][tx + 8 * c];
#pragma unroll
            for (int r = 0; r < 8; r++)
#pragma unroll
                for (int c = 0; c < 8; c++) fma2(acc[r][c], a[r], b[c]);
        }
        __syncthreads();
    }

    float* out = g_gram[blockIdx.z];
#pragma unroll
    for (int r = 0; r < 8; r++) {
        int m = m0 + ty + 16 * r;
#pragma unroll
        for (int c = 0; c < 8; c++) {
            int n = n0 + tx + 8 * c;
            float lo = __uint_as_float((unsigned)(acc[r][c] & 0xffffffffull));
            float hi = __uint_as_float((unsigned)(acc[r][c] >> 32));
            out[(size_t)m * N + n] = lo + hi;
        }
    }
}

// ---------------- kernel 3: hard mining + global margin loss ----------------
// One block per row i. Reads the 4 gram parts (deterministic sum), builds dist,
// reduces argmax-over-pos / argmin-over-neg with FIRST-index tie break.
__global__ void mining_kernel(const void* __restrict__ targets_raw,
                              float* __restrict__ out) {
    const int i = blockIdx.x;
    const int t = threadIdx.x;

    // dtype detection: targets = j//4 -> word[5] is 1 for int32 layout,
    // 0 for int64 layout (high word of entry 2). Reads stay in bounds.
    const int* ip = reinterpret_cast<const int*>(targets_raw);
    const int stride = (ip[5] == 0) ? 2 : 1;   // int64 -> low word every 2 ints

    const int ti  = ip[(size_t)i * stride];
    const float sqi = g_sq[i];
    const float* r0 = g_gram[0] + (size_t)i * N;
    const float* r1 = g_gram[1] + (size_t)i * N;
    const float* r2 = g_gram[2] + (size_t)i * N;
    const float* r3 = g_gram[3] + (size_t)i * N;

    float apv = -3.0e38f; int apj = N;
    float anv =  3.0e38f; int anj = N;

    for (int j = t; j < N; j += 128) {
        float g = r0[j] + r1[j] + r2[j] + r3[j];
        float d = sqrtf(fmaxf(sqi + g_sq[j] - 2.0f * g, 1e-12f));
        if (ip[(size_t)j * stride] == ti) {
            if (d > apv) { apv = d; apj = j; }   // strict > keeps first index
        } else {
            if (d < anv) { anv = d; anj = j; }
        }
    }
    // warp reduce with index tie-break
#pragma unroll
    for (int o = 16; o > 0; o >>= 1) {
        float v = __shfl_down_sync(0xffffffffu, apv, o);
        int   j = __shfl_down_sync(0xffffffffu, apj, o);
        if (v > apv || (v == apv && j < apj)) { apv = v; apj = j; }
        v = __shfl_down_sync(0xffffffffu, anv, o);
        j = __shfl_down_sync(0xffffffffu, anj, o);
        if (v < anv || (v == anv && j < anj)) { anv = v; anj = j; }
    }
    __shared__ float sapv[4], sanv[4];
    __shared__ int   sapj[4], sanj[4];
    if ((t & 31) == 0) {
        int w = t >> 5;
        sapv[w] = apv; sapj[w] = apj;
        sanv[w] = anv; sanj[w] = anj;
    }
    __syncthreads();
    if (t == 0) {
        for (int w = 1; w < 4; w++) {
            if (sapv[w] > apv || (sapv[w] == apv && sapj[w] < apj)) { apv = sapv[w]; apj = sapj[w]; }
            if (sanv[w] < anv || (sanv[w] == anv && sanj[w] < anj)) { anv = sanv[w]; anj = sanj[w]; }
        }
        g_pi[i] = apj;
        g_ni[i] = anj;
        atomicAdd(out, fmaxf(0.0f, MARGIN + apv - anv) * (1.0f / N));
    }
}

// ---------------- kernel 4: local (aligned) loss ----------------
// One block per sample: gather parts of self / hardest-pos / hardest-neg,
// 8x8 tanh(0.5*euclid) matrices, DTW shortest path, margin loss.
__global__ void __launch_bounds__(64)
local_kernel(const float* __restrict__ LF, float* __restrict__ out) {
    __shared__ float sa[PARTS][LDIM + 4];
    __shared__ float sb[PARTS][LDIM + 4];
    __shared__ float sc[PARTS][LDIM + 4];
    __shared__ float dA[PARTS][PARTS];
    __shared__ float dB[PARTS][PARTS];
    __shared__ float res[2];

    const int i = blockIdx.x;
    const int t = threadIdx.x;
    const float* A = LF + (size_t)i        * (LDIM * PARTS);
    const float* B = LF + (size_t)g_pi[i]  * (LDIM * PARTS);
    const float* C = LF + (size_t)g_ni[i]  * (LDIM * PARTS);

    // layout in gmem: [i][d][p] -> part-major in smem: sa[p][d]
    for (int idx = t; idx < LDIM * PARTS; idx += 64) {
        int d = idx >> 3, p = idx & 7;
        sa[p][d] = A[idx];
        sb[p][d] = B[idx];
        sc[p][d] = C[idx];
    }
    __syncthreads();

    const int p = t >> 3, q = t & 7;
    float s1 = 0.0f, s2 = 0.0f;
#pragma unroll 8
    for (int d = 0; d < LDIM; d++) {
        float av = sa[p][d];
        float x = av - sb[q][d]; s1 += x * x;
        float y = av - sc[q][d]; s2 += y * y;
    }
    dA[p][q] = tanhf(0.5f * sqrtf(fmaxf(s1, 1e-12f)));
    dB[p][q] = tanhf(0.5f * sqrtf(fmaxf(s2, 1e-12f)));
    __syncthreads();

    if (t < 2) {
        float (*dm)[PARTS] = (t == 0) ? dA : dB;
        float prev[PARTS];
        prev[0] = 0.0f;
#pragma unroll
        for (int j = 1; j < PARTS; j++) prev[j] = 1e9f;
#pragma unroll
        for (int r = 0; r < PARTS; r++) {
            float left = 1e9f;
#pragma unroll
            for (int j = 0; j < PARTS; j++) {
                float cur = dm[r][j] + fminf(prev[j], left);
                prev[j] = cur;
                left = cur;
            }
        }
        res[t] = prev[PARTS - 1];
    }
    __syncthreads();
    if (t == 0)
        atomicAdd(out + 1, fmaxf(0.0f, MARGIN + res[0] - res[1]) * (1.0f / N));
}

// ---------------- launch ----------------
extern "C" void kernel_launch(void* const* d_in, const int* in_sizes, int n_in,
                              void* d_out, int out_size) {
    const float* X  = (const float*)d_in[0];
    const void*  TG = d_in[1];
    const float* LF = (const float*)d_in[2];
    float* out = (float*)d_out;

    init_out_kernel<<<1, 32>>>(out, out_size < 2 ? out_size : 2);
    norms_kernel<<<N, 256>>>(X);
    dim3 gg(N / BN, N / BM, SPLITS);     // (8, 4, 4) = 128 blocks
    gram_kernel<<<gg, 128>>>(X);
    mining_kernel<<<N, 128>>>(TG, out);
    local_kernel<<<N, 64>>>(LF, out);
}

// round 5
// speedup vs baseline: 1.3344x; 1.3344x over previous
#include <cuda_runtime.h>

#define N      512
#define D      2048
#define LDIM   128
#define PARTS  8
#define SPLITS 8
#define KZ     (D / SPLITS)   // 256
#define BM     64
#define BN     64
#define BK     16
#define NTILES 36             // symmetric tiles (mt<=nt) of 8x8 tile grid
#define MARGIN 0.3f

// ---------------- device scratch (static allocation only) ----------------
__device__ float g_sq[N];
__device__ float g_gram[SPLITS][N * N];   // 8 MB: split-K partial Gram matrices
__device__ float g_gl[N];
__device__ float g_ll[N];

// symmetric tile list: all (mt, nt) with mt <= nt, 8x8 tile grid
__constant__ unsigned char c_mt[NTILES] = {
    0,0,0,0,0,0,0,0, 1,1,1,1,1,1,1, 2,2,2,2,2,2, 3,3,3,3,3, 4,4,4,4, 5,5,5, 6,6, 7};
__constant__ unsigned char c_nt[NTILES] = {
    0,1,2,3,4,5,6,7, 1,2,3,4,5,6,7, 2,3,4,5,6,7, 3,4,5,6,7, 4,5,6,7, 5,6,7, 6,7, 7};

// packed f32x2 FMA: d.lo += a.lo*b.lo ; d.hi += a.hi*b.hi
__device__ __forceinline__ void fma2(unsigned long long& d,
                                     unsigned long long a,
                                     unsigned long long b) {
    asm("fma.rn.f32x2 %0, %1, %2, %0;" : "+l"(d) : "l"(a), "l"(b));
}
__device__ __forceinline__ unsigned long long pack2(float x, float y) {
    unsigned long long u;
    asm("mov.b64 %0, {%1,%2};" : "=l"(u) : "f"(x), "f"(y));
    return u;
}

// ---------------- kernel 1: symmetric split-K Gram + row norms ----------------
// grid (NTILES+1, SPLITS) = (37, 8) = 296 blocks = 148 SMs x 2 co-resident.
// blockIdx.x == NTILES: compute squared norms for 64 rows instead.
__global__ void __launch_bounds__(128, 2)
gram_norms_kernel(const float* __restrict__ X) {
    const int split = blockIdx.y;

    if (blockIdx.x == NTILES) {
        // norms for rows split*64 .. split*64+63 (2 threads per row)
        const int row  = split * 64 + (threadIdx.x >> 1);
        const int half = threadIdx.x & 1;
        const float4* x4 = reinterpret_cast<const float4*>(X + (size_t)row * D)
                           + half * (D / 8);
        float s = 0.0f;
#pragma unroll 8
        for (int k = 0; k < D / 8; k++) {
            float4 v = x4[k];
            s += v.x * v.x + v.y * v.y + v.z * v.z + v.w * v.w;
        }
        s += __shfl_xor_sync(0xffffffffu, s, 1);
        if (half == 0) g_sq[row] = s;
        return;
    }

    __shared__ unsigned long long As[BK / 2][BM + 1];  // [8][65] k even/odd packed
    __shared__ unsigned long long Bs[BK / 2][BN + 1];

    const int tid = threadIdx.x;
    const int tx  = tid & 7;    // 0..7  (col group)
    const int ty  = tid >> 3;   // 0..15 (row group)
    const int m0  = (int)c_mt[blockIdx.x] * BM;
    const int n0  = (int)c_nt[blockIdx.x] * BN;
    const int kz  = split * KZ;

    unsigned long long acc[4][8];
#pragma unroll
    for (int r = 0; r < 4; r++)
#pragma unroll
        for (int c = 0; c < 8; c++) acc[r][c] = 0ull;

#pragma unroll 1
    for (int kc = 0; kc < KZ / BK; kc++) {
        const int kb = kz + kc * BK;
        // A tile: 64 rows x 16 k (256 float4), B tile same: 2 float4 each per thread
#pragma unroll
        for (int l = 0; l < 2; l++) {
            int idx = tid + 128 * l;
            int row = idx >> 2;
            int c4  = idx & 3;
            float4 v = *reinterpret_cast<const float4*>(
                X + (size_t)(m0 + row) * D + kb + c4 * 4);
            As[c4 * 2][row]     = pack2(v.x, v.y);
            As[c4 * 2 + 1][row] = pack2(v.z, v.w);
            float4 w = *reinterpret_cast<const float4*>(
                X + (size_t)(n0 + row) * D + kb + c4 * 4);
            Bs[c4 * 2][row]     = pack2(w.x, w.y);
            Bs[c4 * 2 + 1][row] = pack2(w.z, w.w);
        }
        __syncthreads();
#pragma unroll
        for (int k2 = 0; k2 < BK / 2; k2++) {
            unsigned long long a[4], b[8];
#pragma unroll
            for (int r = 0; r < 4; r++) a[r] = As[k2][ty + 16 * r];
#pragma unroll
            for (int c = 0; c < 8; c++) b[c] = Bs[k2][tx + 8 * c];
#pragma unroll
            for (int r = 0; r < 4; r++)
#pragma unroll
                for (int c = 0; c < 8; c++) fma2(acc[r][c], a[r], b[c]);
        }
        __syncthreads();
    }

    // write tile + mirrored tile (values bitwise identical: same k-order, a*b==b*a)
    float* out = g_gram[split];
#pragma unroll
    for (int r = 0; r < 4; r++) {
        int m = m0 + ty + 16 * r;
#pragma unroll
        for (int c = 0; c < 8; c++) {
            int n = n0 + tx + 8 * c;
            float lo = __uint_as_float((unsigned)(acc[r][c] & 0xffffffffull));
            float hi = __uint_as_float((unsigned)(acc[r][c] >> 32));
            float v = lo + hi;
            out[(size_t)m * N + n] = v;
            out[(size_t)n * N + m] = v;
        }
    }
}

// ---------------- kernel 2: fused hard mining + local DTW loss ----------------
// One block per row i. No atomics: per-row losses go to g_gl / g_ll.
__global__ void __launch_bounds__(128)
mine_local_kernel(const void* __restrict__ targets_raw,
                  const float* __restrict__ LF) {
    const int i = blockIdx.x;
    const int t = threadIdx.x;

    // dtype detection: targets = j//4 -> word[5] is nonzero for int32 layout,
    // 0 for int64 layout (high word of entry 2). Reads stay in bounds.
    const int* ip = reinterpret_cast<const int*>(targets_raw);
    const int stride = (ip[5] == 0) ? 2 : 1;

    const int   ti  = ip[(size_t)i * stride];
    const float sqi = g_sq[i];

    float apv = -3.0e38f; int apj = N;
    float anv =  3.0e38f; int anj = N;

    for (int j = t; j < N; j += 128) {
        float g = 0.0f;
#pragma unroll
        for (int s = 0; s < SPLITS; s++) g += g_gram[s][(size_t)i * N + j];
        float d = sqrtf(fmaxf(sqi + g_sq[j] - 2.0f * g, 1e-12f));
        if (ip[(size_t)j * stride] == ti) {
            if (d > apv) { apv = d; apj = j; }   // strict > keeps first index
        } else {
            if (d < anv) { anv = d; anj = j; }
        }
    }
#pragma unroll
    for (int o = 16; o > 0; o >>= 1) {
        float v = __shfl_down_sync(0xffffffffu, apv, o);
        int   j = __shfl_down_sync(0xffffffffu, apj, o);
        if (v > apv || (v == apv && j < apj)) { apv = v; apj = j; }
        v = __shfl_down_sync(0xffffffffu, anv, o);
        j = __shfl_down_sync(0xffffffffu, anj, o);
        if (v < anv || (v == anv && j < anj)) { anv = v; anj = j; }
    }
    __shared__ float sapv[4], sanv[4];
    __shared__ int   sapj[4], sanj[4];
    __shared__ int   s_pi, s_ni;
    if ((t & 31) == 0) {
        int w = t >> 5;
        sapv[w] = apv; sapj[w] = apj;
        sanv[w] = anv; sanj[w] = anj;
    }
    __syncthreads();
    if (t == 0) {
        for (int w = 1; w < 4; w++) {
            if (sapv[w] > apv || (sapv[w] == apv && sapj[w] < apj)) { apv = sapv[w]; apj = sapj[w]; }
            if (sanv[w] < anv || (sanv[w] == anv && sanj[w] < anj)) { anv = sanv[w]; anj = sanj[w]; }
        }
        s_pi = apj;
        s_ni = anj;
        g_gl[i] = fmaxf(0.0f, MARGIN + apv - anv);
    }
    __syncthreads();

    // ---- local aligned (DTW) loss on parts of (i, hardest-pos, hardest-neg) ----
    __shared__ float sa[PARTS][LDIM + 4];
    __shared__ float sb[PARTS][LDIM + 4];
    __shared__ float sc[PARTS][LDIM + 4];
    __shared__ float dA[PARTS][PARTS];
    __shared__ float dB[PARTS][PARTS];
    __shared__ float res[2];

    const float* A = LF + (size_t)i    * (LDIM * PARTS);
    const float* B = LF + (size_t)s_pi * (LDIM * PARTS);
    const float* C = LF + (size_t)s_ni * (LDIM * PARTS);

    // gmem layout: [i][d][p] -> part-major in smem: sa[p][d]
    for (int idx = t; idx < LDIM * PARTS; idx += 128) {
        int d = idx >> 3, p = idx & 7;
        sa[p][d] = A[idx];
        sb[p][d] = B[idx];
        sc[p][d] = C[idx];
    }
    __syncthreads();

    if (t < 64) {
        const int p = t >> 3, q = t & 7;
        float s1 = 0.0f, s2 = 0.0f;
#pragma unroll 8
        for (int d = 0; d < LDIM; d++) {
            float av = sa[p][d];
            float x = av - sb[q][d]; s1 += x * x;
            float y = av - sc[q][d]; s2 += y * y;
        }
        dA[p][q] = tanhf(0.5f * sqrtf(fmaxf(s1, 1e-12f)));
        dB[p][q] = tanhf(0.5f * sqrtf(fmaxf(s2, 1e-12f)));
    }
    __syncthreads();

    if (t < 2) {
        float (*dm)[PARTS] = (t == 0) ? dA : dB;
        float prev[PARTS];
        prev[0] = 0.0f;
#pragma unroll
        for (int j = 1; j < PARTS; j++) prev[j] = 1e9f;
#pragma unroll
        for (int r = 0; r < PARTS; r++) {
            float left = 1e9f;
#pragma unroll
            for (int j = 0; j < PARTS; j++) {
                float cur = dm[r][j] + fminf(prev[j], left);
                prev[j] = cur;
                left = cur;
            }
        }
        res[t] = prev[PARTS - 1];
    }
    __syncthreads();
    if (t == 0)
        g_ll[i] = fmaxf(0.0f, MARGIN + res[0] - res[1]);
}

// ---------------- kernel 3: deterministic final reduction ----------------
__global__ void reduce_kernel(float* __restrict__ out) {
    const int t = threadIdx.x;   // 512 threads
    float a = g_gl[t];
    float b = g_ll[t];
#pragma unroll
    for (int o = 16; o > 0; o >>= 1) {
        a += __shfl_down_sync(0xffffffffu, a, o);
        b += __shfl_down_sync(0xffffffffu, b, o);
    }
    __shared__ float wa[16], wb[16];
    if ((t & 31) == 0) { wa[t >> 5] = a; wb[t >> 5] = b; }
    __syncthreads();
    if (t < 16) {
        a = wa[t]; b = wb[t];
#pragma unroll
        for (int o = 8; o > 0; o >>= 1) {
            a += __shfl_down_sync(0xffffu, a, o);
            b += __shfl_down_sync(0xffffu, b, o);
        }
        if (t == 0) {
            out[0] = a * (1.0f / N);
            out[1] = b * (1.0f / N);
        }
    }
}

// ---------------- launch ----------------
extern "C" void kernel_launch(void* const* d_in, const int* in_sizes, int n_in,
                              void* d_out, int out_size) {
    const float* X  = (const float*)d_in[0];
    const void*  TG = d_in[1];
    const float* LF = (const float*)d_in[2];
    float* out = (float*)d_out;

    dim3 gg(NTILES + 1, SPLITS);          // 37 x 8 = 296 blocks = 148 SMs x 2
    gram_norms_kernel<<<gg, 128>>>(X);
    mine_local_kernel<<<N, 128>>>(TG, LF);
    reduce_kernel<<<1, 512>>>(out);
}